// round 6
// baseline (speedup 1.0000x reference)
#include <cuda_runtime.h>
#include <cuda_fp16.h>
#include <math.h>
#include <string.h>

#define BB 16
#define NN 512
#define DD 12
#define HID 32
#define HEADS 4
#define CC 8
#define BN (BB*NN)        // 8192
#define NW (NN/32)        // 16 mask words per column

// ---------------- scratch (no allocs allowed) ----------------
__device__ float    d_g[BN*HID];          // g features (1 MB)
__device__ float2   d_e12[BN*HEADS];      // (e^{as}, e^{0.2 as}) per (node, head)
__device__ float    d_ad[BN*HEADS];       // a_dst per node
__device__ __half2  d_tiH2[(HID/2)*BN];   // ti (b1 folded), half2 packed by h-pair
__device__ __half2  d_tjH2[(HID/2)*BN];   // tj, half2 packed by h-pair
__device__ unsigned d_maskT[BB*NN*NW];    // bit-packed (adj|eye) columns

// ---------------- packed f32x2 helpers ----------------
__device__ __forceinline__ unsigned long long f2u(float2 v) {
    unsigned long long u; memcpy(&u, &v, 8); return u;
}
__device__ __forceinline__ float2 u2f(unsigned long long u) {
    float2 v; memcpy(&v, &u, 8); return v;
}
__device__ __forceinline__ float2 ffma2(float2 a, float2 b, float2 c) {
    unsigned long long d;
    asm("fma.rn.f32x2 %0, %1, %2, %3;" : "=l"(d) : "l"(f2u(a)), "l"(f2u(b)), "l"(f2u(c)));
    return u2f(d);
}

// ---------------- fused kernel 0: mask transpose (blocks 0..4095) + node features ----------------
__global__ void __launch_bounds__(256) k01(const int* __restrict__ adj,
                                           const float* __restrict__ x,
                                           const float* __restrict__ Wp,
                                           const float* __restrict__ bp,
                                           const float* __restrict__ Wg,
                                           const float* __restrict__ att_src,
                                           const float* __restrict__ att_dst) {
    int blk = blockIdx.x;
    if (blk < 4096) {
        // ---- mask transpose + bit-pack ----
        __shared__ int s[32][33];
        int b = blk >> 8;
        int tile = blk & 255;
        int i0 = (tile >> 4) * 32;
        int j0 = (tile & 15) * 32;
        int tx = threadIdx.x & 31, ty = threadIdx.x >> 5;   // 8 row-groups
#pragma unroll
        for (int r = 0; r < 4; r++) {
            int row = ty + r*8;
            s[row][tx] = adj[((b*NN + i0 + row)*NN) + j0 + tx];   // coalesced in tx=j
        }
        __syncthreads();
#pragma unroll
        for (int c = 0; c < 4; c++) {
            int jl = ty*4 + c;
            int v = s[tx][jl];
            bool m = (v != 0) || ((i0 + tx) == (j0 + jl));
            unsigned w = __ballot_sync(0xffffffffu, m);
            if (tx == 0)
                d_maskT[(b*NN + j0 + jl)*NW + (i0 >> 5)] = w;
        }
    } else {
        // ---- node features: 128 blocks x 256 threads = BN*4 ----
        __shared__ float sWp[HID*DD];
        __shared__ float sbp[HID];
        __shared__ float sWg[HID*HID];
        __shared__ float sas[HID];
        __shared__ float sad[HID];
        int t = threadIdx.x;
        for (int i = t; i < HID*DD;  i += 256) sWp[i] = Wp[i];
        for (int i = t; i < HID*HID; i += 256) sWg[i] = Wg[i];
        if (t < HID) { sbp[t] = bp[t]; sas[t] = att_src[t]; sad[t] = att_dst[t]; }
        __syncthreads();

        int idx = (blk - 4096) * 256 + t;
        int n = idx >> 2;
        int q = idx & 3;

        float xr[DD];
#pragma unroll
        for (int d = 0; d < DD; d++) xr[d] = x[n*DD + d];

        float h[HID];
#pragma unroll
        for (int k = 0; k < HID; k++) {
            float a = sbp[k];
#pragma unroll
            for (int d = 0; d < DD; d++) a = fmaf(xr[d], sWp[k*DD + d], a);
            h[k] = fmaxf(a, 0.f);
        }

        float gg[CC];
        float asv = 0.f, adv = 0.f;
#pragma unroll
        for (int c = 0; c < CC; c++) {
            int k = q*CC + c;
            float a = 0.f;
#pragma unroll
            for (int d = 0; d < HID; d++) a = fmaf(h[d], sWg[k*HID + d], a);
            gg[c] = a;
            asv = fmaf(a, sas[k], asv);
            adv = fmaf(a, sad[k], adv);
        }
        float4* go = (float4*)&d_g[n*HID + q*CC];
        go[0] = make_float4(gg[0], gg[1], gg[2], gg[3]);
        go[1] = make_float4(gg[4], gg[5], gg[6], gg[7]);
        d_e12[n*HEADS + q] = make_float2(__expf(asv), __expf(0.2f*asv));
        d_ad[n*HEADS + q] = adv;
    }
}

// ---------------- kernel 2: attention + aggregation + fused ti/tj (half2 out) ----------------
// 512 threads: 4 i-groups of 128; (h, jl) within group.
#define JT 32
__global__ void __launch_bounds__(512) k2_attn(const float* __restrict__ bias_g,
                                               const float* __restrict__ W1,
                                               const float* __restrict__ b1) {
    __shared__ float4   sg4[256*8];        // 32 KB; aliased later
    __shared__ float2   sE[256*HEADS];     // 8 KB
    __shared__ unsigned smask[JT*17];
    __shared__ float    sbias[HID];
    __shared__ float    sb1[HID];

    float* salias = (float*)sg4;
    float* sred  = salias;                 // [3 grp][128 wt][9]  = 3456 floats
    float* shg   = salias + 3456;          // [32][33]            = 1056
    float* sW1   = salias + 4512;          // [2048]
    float* sprod = salias;                 // [2][32][32] = 2048, reuses sred region

    int b  = blockIdx.y;
    int j0 = blockIdx.x * JT;
    int t  = threadIdx.x;
    int grp = t >> 7;                      // 0..3
    int wt  = t & 127;
    int h   = wt >> 5;
    int jl  = wt & 31;
    int base = b * NN;

    for (int k = t; k < JT*NW; k += 512) {
        int r = k / NW, c = k % NW;
        smask[r*17 + c] = d_maskT[(base + j0)*NW + k];
    }
    if (t < HID) sbias[t] = bias_g[t];
    else if (t < 2*HID) sb1[t - HID] = b1[t - HID];

    int j = j0 + jl;
    float adv = d_ad[(base + j)*HEADS + h];
    float Ed1 = __expf(adv);
    float Ed2 = __expf(0.2f*adv);

    float2 a01 = {0,0}, a23 = {0,0}, a45 = {0,0}, a67 = {0,0};
    float den = 0.f;

    for (int half = 0; half < 2; half++) {
        const float4* gg = (const float4*)(d_g + (base + half*256)*HID);
        const float2* ee = d_e12 + (base + half*256)*HEADS;
        __syncthreads();
        for (int k = t; k < 256*8; k += 512) sg4[k] = gg[k];
        for (int k = t; k < 256*HEADS; k += 512) sE[k] = ee[k];
        __syncthreads();

#pragma unroll
        for (int iw2 = 0; iw2 < 2; iw2++) {
            int iw = grp*2 + iw2;
            unsigned w = smask[jl*17 + half*8 + iw];
#pragma unroll
            for (int ib = 0; ib < 32; ib++) {
                int il = iw*32 + ib;
                float2 E = sE[il*HEADS + h];
                float f1 = E.x * Ed1;
                float f2 = E.y * Ed2;
                float e0 = (f1 > 1.0f) ? f1 : f2;
                float e  = ((w >> ib) & 1u) ? e0 : 0.f;
                den += e;
                float2 e2 = make_float2(e, e);
                float4 ga = sg4[il*8 + h*2];
                float4 gb = sg4[il*8 + h*2 + 1];
                a01 = ffma2(e2, make_float2(ga.x, ga.y), a01);
                a23 = ffma2(e2, make_float2(ga.z, ga.w), a23);
                a45 = ffma2(e2, make_float2(gb.x, gb.y), a45);
                a67 = ffma2(e2, make_float2(gb.z, gb.w), a67);
            }
        }
    }

    __syncthreads();                 // sg4 reads done; alias region live
    if (grp > 0) {
        float* r = sred + ((grp-1)*128 + wt)*9;
        r[0]=a01.x; r[1]=a01.y; r[2]=a23.x; r[3]=a23.y;
        r[4]=a45.x; r[5]=a45.y; r[6]=a67.x; r[7]=a67.y; r[8]=den;
    }
    for (int k = t; k < HID*2*HID; k += 512) sW1[k] = W1[k];
    __syncthreads();
    if (grp == 0) {
#pragma unroll
        for (int g = 0; g < 3; g++) {
            float* r = sred + (g*128 + wt)*9;
            a01.x+=r[0]; a01.y+=r[1]; a23.x+=r[2]; a23.y+=r[3];
            a45.x+=r[4]; a45.y+=r[5]; a67.x+=r[6]; a67.y+=r[7]; den+=r[8];
        }
        float inv = 1.f / den;       // diagonal always in mask
        float* o = shg + jl*33 + h*CC;
        o[0]=fmaf(a01.x,inv,sbias[h*CC+0]); o[1]=fmaf(a01.y,inv,sbias[h*CC+1]);
        o[2]=fmaf(a23.x,inv,sbias[h*CC+2]); o[3]=fmaf(a23.y,inv,sbias[h*CC+3]);
        o[4]=fmaf(a45.x,inv,sbias[h*CC+4]); o[5]=fmaf(a45.y,inv,sbias[h*CC+5]);
        o[6]=fmaf(a67.x,inv,sbias[h*CC+6]); o[7]=fmaf(a67.y,inv,sbias[h*CC+7]);
    }
    __syncthreads();

    // ti/tj: 2048 values (side, hh, nl); 512 threads -> 4 each
#pragma unroll
    for (int rep = 0; rep < 4; rep++) {
        int o = rep*512 + t;
        int is_tj = o >> 10;
        int hh = (o >> 5) & 31;
        int nl = o & 31;
        float acc = is_tj ? 0.f : sb1[hh];
        const float* wrow = sW1 + hh*64 + is_tj*32;
        const float* hr = shg + nl*33;
#pragma unroll
        for (int d = 0; d < HID; d++) acc = fmaf(hr[d], wrow[d], acc);
        sprod[is_tj*1024 + hh*32 + nl] = acc;
    }
    __syncthreads();

    // pack to half2 by h-pairs and store
    for (int k = t; k < 1024; k += 512) {
        int nl = k & 31;
        int h2 = (k >> 5) & 15;
        int side = k >> 9;
        float lo = sprod[side*1024 + (2*h2)*32 + nl];
        float hi = sprod[side*1024 + (2*h2+1)*32 + nl];
        __half2 v = __floats2half2_rn(lo, hi);
        (side ? d_tjH2 : d_tiH2)[h2*BN + base + j0 + nl] = v;
    }
}

// ---------------- kernel 4: pairwise score, fp16 math ----------------
// grid: 1024 blocks = (16 i-tiles x 4 j-quarters) x 16 b ; 128 threads = j within quarter
#define IT 32
__global__ void __launch_bounds__(128) k4_score(const float* __restrict__ w2,
                                                const float* __restrict__ b2p,
                                                float* __restrict__ out) {
    __shared__ unsigned stiH[IT*20];   // per row: 16 half2 + pad (stride 20 u32)

    int b  = blockIdx.y;
    int gx = blockIdx.x;               // 0..63
    int i0 = (gx >> 2) * IT;
    int jq = gx & 3;
    int t  = threadIdx.x;              // 128 threads
    int base = b * NN;
    int j = jq*128 + t;

    // stage ti rows (half2): 512 entries / 128 threads = 4 each, coalesced on ii
#pragma unroll
    for (int r = 0; r < 4; r++) {
        int k = r*128 + t;
        int ii = k & 31, h2 = k >> 5;
        __half2 v = d_tiH2[h2*BN + base + i0 + ii];
        stiH[ii*20 + h2] = *(unsigned*)&v;
    }

    float b2v = b2p[0];

    __half2 tj2[16];
#pragma unroll
    for (int k = 0; k < 16; k++) tj2[k] = d_tjH2[k*BN + base + j];

    __half2 w2h[16];
#pragma unroll
    for (int k = 0; k < 16; k++) w2h[k] = __floats2half2_rn(w2[2*k], w2[2*k+1]);

    // diagonal-cleared mask word: for i != j, (adj|eye) == adj
    unsigned mw = d_maskT[(base + j)*NW + (i0 >> 5)];
    int dj = j - i0;
    if ((unsigned)dj < 32u) mw &= ~(1u << dj);

    float* orow = out + (size_t)(base + i0)*NN + j;
    const __half2 z2 = __floats2half2_rn(0.f, 0.f);
    __syncthreads();

#pragma unroll 1
    for (int oi = 0; oi < 4; oi++) {
        unsigned mb = mw >> (oi*8);
        float* op = orow + (size_t)oi*8*NN;
        const unsigned* sbase = stiH + oi*8*20;
#pragma unroll
        for (int ii = 0; ii < 8; ii++) {
            const uint4* tip = (const uint4*)(sbase + ii*20);
            uint4 r0 = tip[0], r1 = tip[1], r2 = tip[2], r3 = tip[3];
            __half2 acc0 = z2, acc1 = z2, acc2 = z2, acc3 = z2;
            {
                const __half2* p = (const __half2*)&r0;
#pragma unroll
                for (int q = 0; q < 4; q++)
                    acc0 = __hfma2(__hmax2(__hadd2(p[q], tj2[q]), z2), w2h[q], acc0);
            }
            {
                const __half2* p = (const __half2*)&r1;
#pragma unroll
                for (int q = 0; q < 4; q++)
                    acc1 = __hfma2(__hmax2(__hadd2(p[q], tj2[4+q]), z2), w2h[4+q], acc1);
            }
            {
                const __half2* p = (const __half2*)&r2;
#pragma unroll
                for (int q = 0; q < 4; q++)
                    acc2 = __hfma2(__hmax2(__hadd2(p[q], tj2[8+q]), z2), w2h[8+q], acc2);
            }
            {
                const __half2* p = (const __half2*)&r3;
#pragma unroll
                for (int q = 0; q < 4; q++)
                    acc3 = __hfma2(__hmax2(__hadd2(p[q], tj2[12+q]), z2), w2h[12+q], acc3);
            }
            __half2 s2 = __hadd2(__hadd2(acc0, acc1), __hadd2(acc2, acc3));
            float logit = b2v + __low2float(s2) + __high2float(s2);
            float s = 1.f / (1.f + __expf(-logit));
            op[ii*NN] = ((mb >> ii) & 1u) ? s : 0.f;
        }
    }
}

// ---------------- launcher ----------------
extern "C" void kernel_launch(void* const* d_in, const int* in_sizes, int n_in,
                              void* d_out, int out_size) {
    const float* x       = (const float*)d_in[0];
    const int*   adj     = (const int*)  d_in[1];
    const float* Wp      = (const float*)d_in[2];
    const float* bp      = (const float*)d_in[3];
    const float* Wg      = (const float*)d_in[4];
    const float* att_src = (const float*)d_in[5];
    const float* att_dst = (const float*)d_in[6];
    const float* bias_g  = (const float*)d_in[7];
    const float* W1      = (const float*)d_in[8];
    const float* b1      = (const float*)d_in[9];
    const float* w2      = (const float*)d_in[10];
    const float* b2      = (const float*)d_in[11];
    float* out = (float*)d_out;

    k01<<<4096 + 128, 256>>>(adj, x, Wp, bp, Wg, att_src, att_dst);
    k2_attn<<<dim3(NN/JT, BB), 512>>>(bias_g, W1, b1);
    k4_score<<<dim3(64, BB), 128>>>(w2, b2, out);
}

// round 7
// speedup vs baseline: 1.2066x; 1.2066x over previous
#include <cuda_runtime.h>
#include <cuda_fp16.h>
#include <math.h>
#include <string.h>

#define BB 16
#define NN 512
#define DD 12
#define HID 32
#define HEADS 4
#define CC 8
#define BN (BB*NN)        // 8192
#define NW (NN/32)        // 16 mask words per column

// ---------------- scratch (no allocs allowed) ----------------
__device__ float    d_g[BN*HID];          // g features (1 MB)
__device__ float2   d_e12[BN*HEADS];      // (e^{as}, e^{0.2 as}) per (node, head)
__device__ float    d_ad[BN*HEADS];       // a_dst per node
__device__ __half2  d_tiH2[(HID/2)*BN];   // ti (b1 folded), half2 packed by h-pair
__device__ __half2  d_tjH2[(HID/2)*BN];   // tj, half2 packed by h-pair
__device__ unsigned d_maskT[BB*NN*NW];    // bit-packed (adj|eye) columns

// ---------------- packed f32x2 helpers ----------------
__device__ __forceinline__ unsigned long long f2u(float2 v) {
    unsigned long long u; memcpy(&u, &v, 8); return u;
}
__device__ __forceinline__ float2 u2f(unsigned long long u) {
    float2 v; memcpy(&v, &u, 8); return v;
}
__device__ __forceinline__ float2 ffma2(float2 a, float2 b, float2 c) {
    unsigned long long d;
    asm("fma.rn.f32x2 %0, %1, %2, %3;" : "=l"(d) : "l"(f2u(a)), "l"(f2u(b)), "l"(f2u(c)));
    return u2f(d);
}

// ---------------- kernel T: bandwidth-tuned mask transpose + bit-pack ----------------
// 64x64 adj tiles; each thread: 4 independent LDG.128 (MLP=4); ballot-transpose.
__global__ void __launch_bounds__(256) kT_mask(const int* __restrict__ adj) {
    __shared__ int s[64][65];
    int blk = blockIdx.x;              // 1024 = 16 b * 8 i-tiles * 8 j-tiles
    int b  = blk >> 6;
    int i0 = ((blk >> 3) & 7) * 64;
    int j0 = (blk & 7) * 64;
    int t  = threadIdx.x;
    int r  = t >> 4;                   // 0..15
    int c4 = t & 15;                   // int4 column

    const int4* src = (const int4*)(adj + ((size_t)(b*NN + i0))*NN + j0);
    // 4 independent loads first (MLP), then stores
    int4 v0 = src[(r     )*128 + c4];
    int4 v1 = src[(r + 16)*128 + c4];
    int4 v2 = src[(r + 32)*128 + c4];
    int4 v3 = src[(r + 48)*128 + c4];
    int c = c4*4;
    s[r     ][c]=v0.x; s[r     ][c+1]=v0.y; s[r     ][c+2]=v0.z; s[r     ][c+3]=v0.w;
    s[r + 16][c]=v1.x; s[r + 16][c+1]=v1.y; s[r + 16][c+2]=v1.z; s[r + 16][c+3]=v1.w;
    s[r + 32][c]=v2.x; s[r + 32][c+1]=v2.y; s[r + 32][c+2]=v2.z; s[r + 32][c+3]=v2.w;
    s[r + 48][c]=v3.x; s[r + 48][c+1]=v3.y; s[r + 48][c+2]=v3.z; s[r + 48][c+3]=v3.w;
    __syncthreads();

    // 8 warps cover 2 i-halves x 64 j columns (128 output words)
    int w    = t >> 5;
    int lane = t & 31;
    int hw   = w >> 2;                 // i-half
    int jset = w & 3;                  // group of 16 columns
    int irow = hw*32 + lane;
    int ig   = i0 + irow;              // global i this lane represents
    unsigned keep = 0;
#pragma unroll
    for (int cc2 = 0; cc2 < 16; cc2++) {
        int j = jset*16 + cc2;
        int v = s[irow][j];            // lane*65 -> conflict-free
        bool m = (v != 0) || (ig == (j0 + j));
        unsigned word = __ballot_sync(0xffffffffu, m);
        if (lane == cc2) keep = word;
    }
    if (lane < 16)
        d_maskT[(b*NN + j0 + jset*16 + lane)*NW + (i0 >> 5) + hw] = keep;
}

// ---------------- kernel 1: node features --------------------
__global__ void __launch_bounds__(128) k1_features(const float* __restrict__ x,
                            const float* __restrict__ Wp,
                            const float* __restrict__ bp,
                            const float* __restrict__ Wg,
                            const float* __restrict__ att_src,
                            const float* __restrict__ att_dst) {
    __shared__ float sWp[HID*DD];
    __shared__ float sbp[HID];
    __shared__ float sWg[HID*HID];
    __shared__ float sas[HID];
    __shared__ float sad[HID];
    int t = threadIdx.x;
    for (int i = t; i < HID*DD;  i += 128) sWp[i] = Wp[i];
    for (int i = t; i < HID*HID; i += 128) sWg[i] = Wg[i];
    if (t < HID) { sbp[t] = bp[t]; sas[t] = att_src[t]; sad[t] = att_dst[t]; }
    __syncthreads();

    int idx = blockIdx.x * 128 + t;
    int n = idx >> 2;
    int q = idx & 3;

    float xr[DD];
#pragma unroll
    for (int d = 0; d < DD; d++) xr[d] = x[n*DD + d];

    float h[HID];
#pragma unroll
    for (int k = 0; k < HID; k++) {
        float a = sbp[k];
#pragma unroll
        for (int d = 0; d < DD; d++) a = fmaf(xr[d], sWp[k*DD + d], a);
        h[k] = fmaxf(a, 0.f);
    }

    float gg[CC];
    float asv = 0.f, adv = 0.f;
#pragma unroll
    for (int c = 0; c < CC; c++) {
        int k = q*CC + c;
        float a = 0.f;
#pragma unroll
        for (int d = 0; d < HID; d++) a = fmaf(h[d], sWg[k*HID + d], a);
        gg[c] = a;
        asv = fmaf(a, sas[k], asv);
        adv = fmaf(a, sad[k], adv);
    }
    float4* go = (float4*)&d_g[n*HID + q*CC];
    go[0] = make_float4(gg[0], gg[1], gg[2], gg[3]);
    go[1] = make_float4(gg[4], gg[5], gg[6], gg[7]);
    d_e12[n*HEADS + q] = make_float2(__expf(asv), __expf(0.2f*asv));
    d_ad[n*HEADS + q] = adv;
}

// ---------------- kernel 2: attention + aggregation + fused ti/tj (half2 out) ----------------
// 512 threads: 4 i-groups of 128; (h, jl) within group.
#define JT 32
__global__ void __launch_bounds__(512) k2_attn(const float* __restrict__ bias_g,
                                               const float* __restrict__ W1,
                                               const float* __restrict__ b1) {
    __shared__ float4   sg4[256*8];        // 32 KB; aliased later
    __shared__ float2   sE[256*HEADS];     // 8 KB
    __shared__ unsigned smask[JT*17];
    __shared__ float    sbias[HID];
    __shared__ float    sb1[HID];

    float* salias = (float*)sg4;
    float* sred  = salias;                 // [3 grp][128 wt][9]  = 3456 floats
    float* shg   = salias + 3456;          // [32][33]            = 1056
    float* sW1   = salias + 4512;          // [2048]
    float* sprod = salias;                 // [2][32][32] = 2048, reuses sred region

    int b  = blockIdx.y;
    int j0 = blockIdx.x * JT;
    int t  = threadIdx.x;
    int grp = t >> 7;                      // 0..3
    int wt  = t & 127;
    int h   = wt >> 5;
    int jl  = wt & 31;
    int base = b * NN;

    for (int k = t; k < JT*NW; k += 512) {
        int r = k / NW, c = k % NW;
        smask[r*17 + c] = d_maskT[(base + j0)*NW + k];
    }
    if (t < HID) sbias[t] = bias_g[t];
    else if (t < 2*HID) sb1[t - HID] = b1[t - HID];

    int j = j0 + jl;
    float adv = d_ad[(base + j)*HEADS + h];
    float Ed1 = __expf(adv);
    float Ed2 = __expf(0.2f*adv);

    float2 a01 = {0,0}, a23 = {0,0}, a45 = {0,0}, a67 = {0,0};
    float den = 0.f;

    for (int half = 0; half < 2; half++) {
        const float4* gg = (const float4*)(d_g + (base + half*256)*HID);
        const float2* ee = d_e12 + (base + half*256)*HEADS;
        __syncthreads();
        for (int k = t; k < 256*8; k += 512) sg4[k] = gg[k];
        for (int k = t; k < 256*HEADS; k += 512) sE[k] = ee[k];
        __syncthreads();

#pragma unroll
        for (int iw2 = 0; iw2 < 2; iw2++) {
            int iw = grp*2 + iw2;
            unsigned w = smask[jl*17 + half*8 + iw];
#pragma unroll
            for (int ib = 0; ib < 32; ib++) {
                int il = iw*32 + ib;
                float2 E = sE[il*HEADS + h];
                float f1 = E.x * Ed1;
                float f2 = E.y * Ed2;
                float e0 = (f1 > 1.0f) ? f1 : f2;
                float e  = ((w >> ib) & 1u) ? e0 : 0.f;
                den += e;
                float2 e2 = make_float2(e, e);
                float4 ga = sg4[il*8 + h*2];
                float4 gb = sg4[il*8 + h*2 + 1];
                a01 = ffma2(e2, make_float2(ga.x, ga.y), a01);
                a23 = ffma2(e2, make_float2(ga.z, ga.w), a23);
                a45 = ffma2(e2, make_float2(gb.x, gb.y), a45);
                a67 = ffma2(e2, make_float2(gb.z, gb.w), a67);
            }
        }
    }

    __syncthreads();                 // sg4 reads done; alias region live
    if (grp > 0) {
        float* r = sred + ((grp-1)*128 + wt)*9;
        r[0]=a01.x; r[1]=a01.y; r[2]=a23.x; r[3]=a23.y;
        r[4]=a45.x; r[5]=a45.y; r[6]=a67.x; r[7]=a67.y; r[8]=den;
    }
    for (int k = t; k < HID*2*HID; k += 512) sW1[k] = W1[k];
    __syncthreads();
    if (grp == 0) {
#pragma unroll
        for (int g = 0; g < 3; g++) {
            float* r = sred + (g*128 + wt)*9;
            a01.x+=r[0]; a01.y+=r[1]; a23.x+=r[2]; a23.y+=r[3];
            a45.x+=r[4]; a45.y+=r[5]; a67.x+=r[6]; a67.y+=r[7]; den+=r[8];
        }
        float inv = 1.f / den;       // diagonal always in mask
        float* o = shg + jl*33 + h*CC;
        o[0]=fmaf(a01.x,inv,sbias[h*CC+0]); o[1]=fmaf(a01.y,inv,sbias[h*CC+1]);
        o[2]=fmaf(a23.x,inv,sbias[h*CC+2]); o[3]=fmaf(a23.y,inv,sbias[h*CC+3]);
        o[4]=fmaf(a45.x,inv,sbias[h*CC+4]); o[5]=fmaf(a45.y,inv,sbias[h*CC+5]);
        o[6]=fmaf(a67.x,inv,sbias[h*CC+6]); o[7]=fmaf(a67.y,inv,sbias[h*CC+7]);
    }
    __syncthreads();

    // ti/tj: 2048 values (side, hh, nl); 512 threads -> 4 each
#pragma unroll
    for (int rep = 0; rep < 4; rep++) {
        int o = rep*512 + t;
        int is_tj = o >> 10;
        int hh = (o >> 5) & 31;
        int nl = o & 31;
        float acc = is_tj ? 0.f : sb1[hh];
        const float* wrow = sW1 + hh*64 + is_tj*32;
        const float* hr = shg + nl*33;
#pragma unroll
        for (int d = 0; d < HID; d++) acc = fmaf(hr[d], wrow[d], acc);
        sprod[is_tj*1024 + hh*32 + nl] = acc;
    }
    __syncthreads();

    // pack to half2 by h-pairs and store
    for (int k = t; k < 1024; k += 512) {
        int nl = k & 31;
        int h2 = (k >> 5) & 15;
        int side = k >> 9;
        float lo = sprod[side*1024 + (2*h2)*32 + nl];
        float hi = sprod[side*1024 + (2*h2+1)*32 + nl];
        __half2 v = __floats2half2_rn(lo, hi);
        (side ? d_tjH2 : d_tiH2)[h2*BN + base + j0 + nl] = v;
    }
}

// ---------------- kernel 4: pairwise score, fp16 math ----------------
// grid: (64, 16) blocks of 128 threads; block = (32-i tile) x (128-j quarter)
#define IT 32
__global__ void __launch_bounds__(128) k4_score(const float* __restrict__ w2,
                                                const float* __restrict__ b2p,
                                                float* __restrict__ out) {
    __shared__ unsigned stiH[IT*20];   // per row: 16 half2 + pad (stride 20 u32)

    int b  = blockIdx.y;
    int gx = blockIdx.x;               // 0..63
    int i0 = (gx >> 2) * IT;
    int jq = gx & 3;
    int t  = threadIdx.x;              // 128 threads
    int base = b * NN;
    int j = jq*128 + t;

    // stage ti rows (half2): 512 entries / 128 threads = 4 each, coalesced on ii
#pragma unroll
    for (int r = 0; r < 4; r++) {
        int k = r*128 + t;
        int ii = k & 31, h2 = k >> 5;
        __half2 v = d_tiH2[h2*BN + base + i0 + ii];
        stiH[ii*20 + h2] = *(unsigned*)&v;
    }

    float b2v = b2p[0];

    __half2 tj2[16];
#pragma unroll
    for (int k = 0; k < 16; k++) tj2[k] = d_tjH2[k*BN + base + j];

    __half2 w2h[16];
#pragma unroll
    for (int k = 0; k < 16; k++) w2h[k] = __floats2half2_rn(w2[2*k], w2[2*k+1]);

    // diagonal-cleared mask word: for i != j, (adj|eye) == adj
    unsigned mw = d_maskT[(base + j)*NW + (i0 >> 5)];
    int dj = j - i0;
    if ((unsigned)dj < 32u) mw &= ~(1u << dj);

    float* orow = out + (size_t)(base + i0)*NN + j;
    const __half2 z2 = __floats2half2_rn(0.f, 0.f);
    __syncthreads();

#pragma unroll 1
    for (int oi = 0; oi < 4; oi++) {
        unsigned mb = mw >> (oi*8);
        float* op = orow + (size_t)oi*8*NN;
        const unsigned* sbase = stiH + oi*8*20;
#pragma unroll
        for (int ii = 0; ii < 8; ii++) {
            const uint4* tip = (const uint4*)(sbase + ii*20);
            uint4 r0 = tip[0], r1 = tip[1], r2 = tip[2], r3 = tip[3];
            __half2 acc0 = z2, acc1 = z2, acc2 = z2, acc3 = z2;
            {
                const __half2* p = (const __half2*)&r0;
#pragma unroll
                for (int q = 0; q < 4; q++)
                    acc0 = __hfma2(__hmax2(__hadd2(p[q], tj2[q]), z2), w2h[q], acc0);
            }
            {
                const __half2* p = (const __half2*)&r1;
#pragma unroll
                for (int q = 0; q < 4; q++)
                    acc1 = __hfma2(__hmax2(__hadd2(p[q], tj2[4+q]), z2), w2h[4+q], acc1);
            }
            {
                const __half2* p = (const __half2*)&r2;
#pragma unroll
                for (int q = 0; q < 4; q++)
                    acc2 = __hfma2(__hmax2(__hadd2(p[q], tj2[8+q]), z2), w2h[8+q], acc2);
            }
            {
                const __half2* p = (const __half2*)&r3;
#pragma unroll
                for (int q = 0; q < 4; q++)
                    acc3 = __hfma2(__hmax2(__hadd2(p[q], tj2[12+q]), z2), w2h[12+q], acc3);
            }
            __half2 s2 = __hadd2(__hadd2(acc0, acc1), __hadd2(acc2, acc3));
            float logit = b2v + __low2float(s2) + __high2float(s2);
            float s = 1.f / (1.f + __expf(-logit));
            op[ii*NN] = ((mb >> ii) & 1u) ? s : 0.f;
        }
    }
}

// ---------------- launcher ----------------
extern "C" void kernel_launch(void* const* d_in, const int* in_sizes, int n_in,
                              void* d_out, int out_size) {
    const float* x       = (const float*)d_in[0];
    const int*   adj     = (const int*)  d_in[1];
    const float* Wp      = (const float*)d_in[2];
    const float* bp      = (const float*)d_in[3];
    const float* Wg      = (const float*)d_in[4];
    const float* att_src = (const float*)d_in[5];
    const float* att_dst = (const float*)d_in[6];
    const float* bias_g  = (const float*)d_in[7];
    const float* W1      = (const float*)d_in[8];
    const float* b1      = (const float*)d_in[9];
    const float* w2      = (const float*)d_in[10];
    const float* b2      = (const float*)d_in[11];
    float* out = (float*)d_out;

    kT_mask<<<1024, 256>>>(adj);
    k1_features<<<(BN*4)/128, 128>>>(x, Wp, bp, Wg, att_src, att_dst);
    k2_attn<<<dim3(NN/JT, BB), 512>>>(bias_g, W1, b1);
    k4_score<<<dim3(64, BB), 128>>>(w2, b2, out);
}

// round 11
// speedup vs baseline: 1.2497x; 1.0357x over previous
#include <cuda_runtime.h>
#include <cuda_fp16.h>
#include <math.h>
#include <string.h>

#define BB 16
#define NN 512
#define DD 12
#define HID 32
#define HEADS 4
#define CC 8
#define BN (BB*NN)        // 8192
#define NW (NN/32)        // 16 mask words per column

// ---------------- scratch (no allocs allowed) ----------------
__device__ float    d_g[BN*HID];          // g features (1 MB)
__device__ float2   d_e12[BN*HEADS];      // (e^{as}, e^{0.2 as}) per (node, head)
__device__ float    d_ad[BN*HEADS];       // a_dst per node
__device__ __half2  d_tiH2[(HID/2)*BN];   // ti (b1 folded), half2 packed by h-pair
__device__ __half2  d_tjH2[(HID/2)*BN];   // tj, half2 packed by h-pair
__device__ unsigned d_maskT[BB*NN*NW];    // bit-packed (adj|eye) columns

// ---------------- packed f32x2 helpers ----------------
__device__ __forceinline__ unsigned long long f2u(float2 v) {
    unsigned long long u; memcpy(&u, &v, 8); return u;
}
__device__ __forceinline__ float2 u2f(unsigned long long u) {
    float2 v; memcpy(&v, &u, 8); return v;
}
__device__ __forceinline__ float2 ffma2(float2 a, float2 b, float2 c) {
    unsigned long long d;
    asm("fma.rn.f32x2 %0, %1, %2, %3;" : "=l"(d) : "l"(f2u(a)), "l"(f2u(b)), "l"(f2u(c)));
    return u2f(d);
}

// sigmoid(x) = 0.5*tanh(0.5x) + 0.5 via MUFU.TANH
__device__ __forceinline__ float sigmoid_tanh(float x) {
    float t;
    asm("tanh.approx.f32 %0, %1;" : "=f"(t) : "f"(0.5f * x));
    return fmaf(0.5f, t, 0.5f);
}

// ---------------- kernel T: bandwidth-tuned mask transpose + bit-pack ----------------
// 64x64 adj tiles; each thread: 4 independent LDG.128 (MLP=4); ballot-transpose.
__global__ void __launch_bounds__(256) kT_mask(const int* __restrict__ adj) {
    __shared__ int s[64][65];
    int blk = blockIdx.x;              // 1024 = 16 b * 8 i-tiles * 8 j-tiles
    int b  = blk >> 6;
    int i0 = ((blk >> 3) & 7) * 64;
    int j0 = (blk & 7) * 64;
    int t  = threadIdx.x;
    int r  = t >> 4;                   // 0..15
    int c4 = t & 15;                   // int4 column

    const int4* src = (const int4*)(adj + ((size_t)(b*NN + i0))*NN + j0);
    int4 v0 = src[(r     )*128 + c4];
    int4 v1 = src[(r + 16)*128 + c4];
    int4 v2 = src[(r + 32)*128 + c4];
    int4 v3 = src[(r + 48)*128 + c4];
    int c = c4*4;
    s[r     ][c]=v0.x; s[r     ][c+1]=v0.y; s[r     ][c+2]=v0.z; s[r     ][c+3]=v0.w;
    s[r + 16][c]=v1.x; s[r + 16][c+1]=v1.y; s[r + 16][c+2]=v1.z; s[r + 16][c+3]=v1.w;
    s[r + 32][c]=v2.x; s[r + 32][c+1]=v2.y; s[r + 32][c+2]=v2.z; s[r + 32][c+3]=v2.w;
    s[r + 48][c]=v3.x; s[r + 48][c+1]=v3.y; s[r + 48][c+2]=v3.z; s[r + 48][c+3]=v3.w;
    __syncthreads();

    int w    = t >> 5;
    int lane = t & 31;
    int hw   = w >> 2;                 // i-half
    int jset = w & 3;                  // group of 16 columns
    int irow = hw*32 + lane;
    int ig   = i0 + irow;
    unsigned keep = 0;
#pragma unroll
    for (int cc2 = 0; cc2 < 16; cc2++) {
        int j = jset*16 + cc2;
        int v = s[irow][j];
        bool m = (v != 0) || (ig == (j0 + j));
        unsigned word = __ballot_sync(0xffffffffu, m);
        if (lane == cc2) keep = word;
    }
    if (lane < 16)
        d_maskT[(b*NN + j0 + jset*16 + lane)*NW + (i0 >> 5) + hw] = keep;
}

// ---------------- kernel 1: node features --------------------
__global__ void __launch_bounds__(128) k1_features(const float* __restrict__ x,
                            const float* __restrict__ Wp,
                            const float* __restrict__ bp,
                            const float* __restrict__ Wg,
                            const float* __restrict__ att_src,
                            const float* __restrict__ att_dst) {
    __shared__ float sWp[HID*DD];
    __shared__ float sbp[HID];
    __shared__ float sWg[HID*HID];
    __shared__ float sas[HID];
    __shared__ float sad[HID];
    int t = threadIdx.x;
    for (int i = t; i < HID*DD;  i += 128) sWp[i] = Wp[i];
    for (int i = t; i < HID*HID; i += 128) sWg[i] = Wg[i];
    if (t < HID) { sbp[t] = bp[t]; sas[t] = att_src[t]; sad[t] = att_dst[t]; }
    __syncthreads();

    int idx = blockIdx.x * 128 + t;
    int n = idx >> 2;
    int q = idx & 3;

    float xr[DD];
#pragma unroll
    for (int d = 0; d < DD; d++) xr[d] = x[n*DD + d];

    float h[HID];
#pragma unroll
    for (int k = 0; k < HID; k++) {
        float a = sbp[k];
#pragma unroll
        for (int d = 0; d < DD; d++) a = fmaf(xr[d], sWp[k*DD + d], a);
        h[k] = fmaxf(a, 0.f);
    }

    float gg[CC];
    float asv = 0.f, adv = 0.f;
#pragma unroll
    for (int c = 0; c < CC; c++) {
        int k = q*CC + c;
        float a = 0.f;
#pragma unroll
        for (int d = 0; d < HID; d++) a = fmaf(h[d], sWg[k*HID + d], a);
        gg[c] = a;
        asv = fmaf(a, sas[k], asv);
        adv = fmaf(a, sad[k], adv);
    }
    float4* go = (float4*)&d_g[n*HID + q*CC];
    go[0] = make_float4(gg[0], gg[1], gg[2], gg[3]);
    go[1] = make_float4(gg[4], gg[5], gg[6], gg[7]);
    d_e12[n*HEADS + q] = make_float2(__expf(asv), __expf(0.2f*asv));
    d_ad[n*HEADS + q] = adv;
}

// ---------------- kernel 2: attention + aggregation + fused ti/tj (half2 out) ----------------
// 512 threads: 4 i-groups of 128; (h, jl) within group.
#define JT 32
__global__ void __launch_bounds__(512) k2_attn(const float* __restrict__ bias_g,
                                               const float* __restrict__ W1,
                                               const float* __restrict__ b1) {
    __shared__ float4   sg4[256*8];        // 32 KB; aliased later
    __shared__ float2   sE[256*HEADS];     // 8 KB
    __shared__ unsigned smask[JT*17];
    __shared__ float    sbias[HID];
    __shared__ float    sb1[HID];

    float* salias = (float*)sg4;
    float* sred  = salias;                 // [3 grp][128 wt][9]
    float* shg   = salias + 3456;          // [32][33]
    float* sW1   = salias + 4512;          // [2048]
    float* sprod = salias;                 // [2][32][32], reuses sred region

    int b  = blockIdx.y;
    int j0 = blockIdx.x * JT;
    int t  = threadIdx.x;
    int grp = t >> 7;                      // 0..3
    int wt  = t & 127;
    int h   = wt >> 5;
    int jl  = wt & 31;
    int base = b * NN;

    for (int k = t; k < JT*NW; k += 512) {
        int r = k / NW, c = k % NW;
        smask[r*17 + c] = d_maskT[(base + j0)*NW + k];
    }
    if (t < HID) sbias[t] = bias_g[t];
    else if (t < 2*HID) sb1[t - HID] = b1[t - HID];

    int j = j0 + jl;
    float adv = d_ad[(base + j)*HEADS + h];
    float Ed1 = __expf(adv);
    float Ed2 = __expf(0.2f*adv);

    float2 a01 = {0,0}, a23 = {0,0}, a45 = {0,0}, a67 = {0,0};
    float den = 0.f;

    for (int half = 0; half < 2; half++) {
        const float4* gg = (const float4*)(d_g + (base + half*256)*HID);
        const float2* ee = d_e12 + (base + half*256)*HEADS;
        __syncthreads();
        for (int k = t; k < 256*8; k += 512) sg4[k] = gg[k];
        for (int k = t; k < 256*HEADS; k += 512) sE[k] = ee[k];
        __syncthreads();

#pragma unroll
        for (int iw2 = 0; iw2 < 2; iw2++) {
            int iw = grp*2 + iw2;
            unsigned w = smask[jl*17 + half*8 + iw];
#pragma unroll
            for (int ib = 0; ib < 32; ib++) {
                int il = iw*32 + ib;
                float2 E = sE[il*HEADS + h];
                float f1 = E.x * Ed1;
                float f2 = E.y * Ed2;
                float e0 = (f1 > 1.0f) ? f1 : f2;
                float e  = ((w >> ib) & 1u) ? e0 : 0.f;
                den += e;
                float2 e2 = make_float2(e, e);
                float4 ga = sg4[il*8 + h*2];
                float4 gb = sg4[il*8 + h*2 + 1];
                a01 = ffma2(e2, make_float2(ga.x, ga.y), a01);
                a23 = ffma2(e2, make_float2(ga.z, ga.w), a23);
                a45 = ffma2(e2, make_float2(gb.x, gb.y), a45);
                a67 = ffma2(e2, make_float2(gb.z, gb.w), a67);
            }
        }
    }

    __syncthreads();                 // sg4 reads done; alias region live
    if (grp > 0) {
        float* r = sred + ((grp-1)*128 + wt)*9;
        r[0]=a01.x; r[1]=a01.y; r[2]=a23.x; r[3]=a23.y;
        r[4]=a45.x; r[5]=a45.y; r[6]=a67.x; r[7]=a67.y; r[8]=den;
    }
    for (int k = t; k < HID*2*HID; k += 512) sW1[k] = W1[k];
    __syncthreads();
    if (grp == 0) {
#pragma unroll
        for (int g = 0; g < 3; g++) {
            float* r = sred + (g*128 + wt)*9;
            a01.x+=r[0]; a01.y+=r[1]; a23.x+=r[2]; a23.y+=r[3];
            a45.x+=r[4]; a45.y+=r[5]; a67.x+=r[6]; a67.y+=r[7]; den+=r[8];
        }
        float inv = 1.f / den;       // diagonal always in mask
        float* o = shg + jl*33 + h*CC;
        o[0]=fmaf(a01.x,inv,sbias[h*CC+0]); o[1]=fmaf(a01.y,inv,sbias[h*CC+1]);
        o[2]=fmaf(a23.x,inv,sbias[h*CC+2]); o[3]=fmaf(a23.y,inv,sbias[h*CC+3]);
        o[4]=fmaf(a45.x,inv,sbias[h*CC+4]); o[5]=fmaf(a45.y,inv,sbias[h*CC+5]);
        o[6]=fmaf(a67.x,inv,sbias[h*CC+6]); o[7]=fmaf(a67.y,inv,sbias[h*CC+7]);
    }
    __syncthreads();

    // ti/tj: 2048 values (side, hh, nl); 512 threads -> 4 each
#pragma unroll
    for (int rep = 0; rep < 4; rep++) {
        int o = rep*512 + t;
        int is_tj = o >> 10;
        int hh = (o >> 5) & 31;
        int nl = o & 31;
        float acc = is_tj ? 0.f : sb1[hh];
        const float* wrow = sW1 + hh*64 + is_tj*32;
        const float* hr = shg + nl*33;
#pragma unroll
        for (int d = 0; d < HID; d++) acc = fmaf(hr[d], wrow[d], acc);
        sprod[is_tj*1024 + hh*32 + nl] = acc;
    }
    __syncthreads();

    // pack to half2 by h-pairs and store
    for (int k = t; k < 1024; k += 512) {
        int nl = k & 31;
        int h2 = (k >> 5) & 15;
        int side = k >> 9;
        float lo = sprod[side*1024 + (2*h2)*32 + nl];
        float hi = sprod[side*1024 + (2*h2+1)*32 + nl];
        __half2 v = __floats2half2_rn(lo, hi);
        (side ? d_tjH2 : d_tiH2)[h2*BN + base + j0 + nl] = v;
    }
}

// ---------------- kernel 4: pairwise score, fp16 math ----------------
// grid: (64, 16) blocks of 128 threads; block = (32-i tile) x (128-j quarter)
// w2 lives in shared (uniform LDS broadcast) to cut register pressure -> occupancy.
#define IT 32
__global__ void __launch_bounds__(128, 10) k4_score(const float* __restrict__ w2,
                                                    const float* __restrict__ b2p,
                                                    float* __restrict__ out) {
    __shared__ unsigned stiH[IT*20];   // per row: 16 half2 + pad (stride 20 u32)
    __shared__ __half2  sw2h[16];

    int b  = blockIdx.y;
    int gx = blockIdx.x;               // 0..63
    int i0 = (gx >> 2) * IT;
    int jq = gx & 3;
    int t  = threadIdx.x;              // 128 threads
    int base = b * NN;
    int j = jq*128 + t;

    // stage ti rows (half2): 512 entries / 128 threads = 4 each, coalesced on ii
#pragma unroll
    for (int r = 0; r < 4; r++) {
        int k = r*128 + t;
        int ii = k & 31, h2 = k >> 5;
        __half2 v = d_tiH2[h2*BN + base + i0 + ii];
        stiH[ii*20 + h2] = *(unsigned*)&v;
    }
    if (t < 16) sw2h[t] = __floats2half2_rn(w2[2*t], w2[2*t+1]);

    float b2v = b2p[0];

    __half2 tj2[16];
#pragma unroll
    for (int k = 0; k < 16; k++) tj2[k] = d_tjH2[k*BN + base + j];

    // diagonal-cleared mask word: for i != j, (adj|eye) == adj
    unsigned mw = d_maskT[(base + j)*NW + (i0 >> 5)];
    int dj = j - i0;
    if ((unsigned)dj < 32u) mw &= ~(1u << dj);

    float* orow = out + (size_t)(base + i0)*NN + j;
    const __half2 z2 = __floats2half2_rn(0.f, 0.f);
    __syncthreads();

#pragma unroll 1
    for (int oi = 0; oi < 4; oi++) {
        unsigned mb = mw >> (oi*8);
        float* op = orow + (size_t)oi*8*NN;
        const unsigned* sbase = stiH + oi*8*20;
#pragma unroll
        for (int ii = 0; ii < 8; ii++) {
            const __half2* tip = (const __half2*)(sbase + ii*20);
            __half2 acc0 = z2, acc1 = z2, acc2 = z2, acc3 = z2;
#pragma unroll
            for (int q = 0; q < 4; q++)
                acc0 = __hfma2(__hmax2(__hadd2(tip[q], tj2[q]), z2), sw2h[q], acc0);
#pragma unroll
            for (int q = 4; q < 8; q++)
                acc1 = __hfma2(__hmax2(__hadd2(tip[q], tj2[q]), z2), sw2h[q], acc1);
#pragma unroll
            for (int q = 8; q < 12; q++)
                acc2 = __hfma2(__hmax2(__hadd2(tip[q], tj2[q]), z2), sw2h[q], acc2);
#pragma unroll
            for (int q = 12; q < 16; q++)
                acc3 = __hfma2(__hmax2(__hadd2(tip[q], tj2[q]), z2), sw2h[q], acc3);
            __half2 s2 = __hadd2(__hadd2(acc0, acc1), __hadd2(acc2, acc3));
            float logit = b2v + __low2float(s2) + __high2float(s2);
            float s = sigmoid_tanh(logit);
            op[ii*NN] = ((mb >> ii) & 1u) ? s : 0.f;
        }
    }
}

// ---------------- launcher ----------------
extern "C" void kernel_launch(void* const* d_in, const int* in_sizes, int n_in,
                              void* d_out, int out_size) {
    const float* x       = (const float*)d_in[0];
    const int*   adj     = (const int*)  d_in[1];
    const float* Wp      = (const float*)d_in[2];
    const float* bp      = (const float*)d_in[3];
    const float* Wg      = (const float*)d_in[4];
    const float* att_src = (const float*)d_in[5];
    const float* att_dst = (const float*)d_in[6];
    const float* bias_g  = (const float*)d_in[7];
    const float* W1      = (const float*)d_in[8];
    const float* b1      = (const float*)d_in[9];
    const float* w2      = (const float*)d_in[10];
    const float* b2      = (const float*)d_in[11];
    float* out = (float*)d_out;

    kT_mask<<<1024, 256>>>(adj);
    k1_features<<<(BN*4)/128, 128>>>(x, Wp, bp, Wg, att_src, att_dst);
    k2_attn<<<dim3(NN/JT, BB), 512>>>(bias_g, W1, b1);
    k4_score<<<dim3(64, BB), 128>>>(w2, b2, out);
}